// round 1
// baseline (speedup 1.0000x reference)
#include <cuda_runtime.h>
#include <cstdint>

// ---------------------------------------------------------------------------
// GLA block: B=8, T=4096, D=1024, H=4, Dk=128, Dv=256
//   q = (x@Wq)*Dk^-0.5 ; k = x@Wk ; v = x@Wv ; g = x@Wg
//   decay = exp(log_sigmoid(x@(gk_w1@gk_w2) + b2)/16)
//   S_t = decay_t (x) S_{t-1} + k_t^T v_t ;  o_t = q_t @ S_t
//   o = RMSNorm(o)*g_norm_w * g*sigmoid(g) ; out = o @ Wo
// ---------------------------------------------------------------------------

#define BB   8
#define TT   4096
#define DD   1024
#define HH   4
#define DK   128
#define DV   256
#define MM   (BB*TT)          // 32768
#define QSCALE 0.08838834764831845f

// Scratch (device globals: allocation-free per harness rules)
__device__ float g_q  [MM * 512];
__device__ float g_k  [MM * 512];
__device__ float g_v  [MM * 1024];
__device__ float g_g  [MM * 1024];
__device__ float g_dcy[MM * 512];
__device__ float g_o  [MM * 1024];
__device__ float g_weff[1024 * 512];

// ---------------------------------------------------------------------------
// Weff = gk_w1 @ gk_w2   (1024x16 @ 16x512)
// ---------------------------------------------------------------------------
__global__ void weff_kernel(const float* __restrict__ w1,
                            const float* __restrict__ w2)
{
    int idx = blockIdx.x * blockDim.x + threadIdx.x;   // < 1024*512
    int kk = idx >> 9;
    int n  = idx & 511;
    float s = 0.f;
#pragma unroll
    for (int r = 0; r < 16; r++)
        s += w1[kk * 16 + r] * w2[r * 512 + n];
    g_weff[idx] = s;
}

// ---------------------------------------------------------------------------
// Tiled SGEMM: C[M,N] = A[M,K] @ W[K,N], row-major, K=1024, M=32768
// mode 0: C = acc*scale
// mode 1: z = acc + bias[n]; C = exp(-softplus(-z)/16)   (gate decay)
// BM=BN=128, BK=16, 256 threads, 8x8 per thread
// ---------------------------------------------------------------------------
__global__ __launch_bounds__(256)
void sgemm_k(const float* __restrict__ A, const float* __restrict__ W,
             float* __restrict__ C, int K, int N, float scale,
             const float* __restrict__ bias, int mode)
{
    __shared__ __align__(16) float As[16][132];   // transposed, padded
    __shared__ __align__(16) float Bs[16][128];

    int bx = blockIdx.x;         // N tile
    int by = blockIdx.y;         // M tile
    int tid = threadIdx.x;
    int tx = tid & 15;           // 16 col-groups
    int ty = tid >> 4;           // 16 row-groups

    const float* Ab = A + (size_t)by * 128 * K;
    const float* Bb = W + (size_t)bx * 128;

    int arow  = tid >> 2;            // 0..63
    int acol4 = (tid & 3) * 4;       // 0,4,8,12
    int brow  = tid >> 5;            // 0..7
    int bcol4 = (tid & 31) * 4;      // 0..124

    float acc[8][8];
#pragma unroll
    for (int i = 0; i < 8; i++)
#pragma unroll
        for (int j = 0; j < 8; j++) acc[i][j] = 0.f;

    for (int k0 = 0; k0 < K; k0 += 16) {
#pragma unroll
        for (int i = 0; i < 2; i++) {
            int r = arow + i * 64;
            float4 va = *(const float4*)(Ab + (size_t)r * K + k0 + acol4);
            As[acol4 + 0][r] = va.x;
            As[acol4 + 1][r] = va.y;
            As[acol4 + 2][r] = va.z;
            As[acol4 + 3][r] = va.w;
        }
#pragma unroll
        for (int i = 0; i < 2; i++) {
            int r = brow + i * 8;
            *(float4*)(&Bs[r][bcol4]) =
                *(const float4*)(Bb + (size_t)(k0 + r) * N + bcol4);
        }
        __syncthreads();
#pragma unroll
        for (int kk = 0; kk < 16; kk++) {
            float4 a0 = *(const float4*)(&As[kk][ty * 8]);
            float4 a1 = *(const float4*)(&As[kk][ty * 8 + 4]);
            float4 b0 = *(const float4*)(&Bs[kk][tx * 8]);
            float4 b1 = *(const float4*)(&Bs[kk][tx * 8 + 4]);
            float ar[8] = {a0.x, a0.y, a0.z, a0.w, a1.x, a1.y, a1.z, a1.w};
            float br[8] = {b0.x, b0.y, b0.z, b0.w, b1.x, b1.y, b1.z, b1.w};
#pragma unroll
            for (int i = 0; i < 8; i++)
#pragma unroll
                for (int j = 0; j < 8; j++)
                    acc[i][j] += ar[i] * br[j];
        }
        __syncthreads();
    }

    int crow0 = by * 128 + ty * 8;
    int ccol0 = bx * 128 + tx * 8;
#pragma unroll
    for (int i = 0; i < 8; i++) {
        float out[8];
        if (mode == 0) {
#pragma unroll
            for (int j = 0; j < 8; j++) out[j] = acc[i][j] * scale;
        } else {
#pragma unroll
            for (int j = 0; j < 8; j++) {
                float z  = acc[i][j] + bias[ccol0 + j];
                float sp = fmaxf(-z, 0.f) + log1pf(expf(-fabsf(z)));
                out[j]   = expf(-sp * 0.0625f);
            }
        }
        float* Cp = C + (size_t)(crow0 + i) * N + ccol0;
        *(float4*)(Cp)     = make_float4(out[0], out[1], out[2], out[3]);
        *(float4*)(Cp + 4) = make_float4(out[4], out[5], out[6], out[7]);
    }
}

// ---------------------------------------------------------------------------
// Gated linear attention recurrence.
// Grid: B*H*(Dv/32) = 256 blocks. Block: 128 threads.
// thread = (c = tid&31 : v-column, qr = tid>>5 : 32-row k-slice)
// S[32] in registers per thread. Per-step q/k/decay smem reads are warp-
// broadcast (all lanes of a warp share qr). Next step's globals prefetched
// into registers to hide DRAM latency behind compute.
// ---------------------------------------------------------------------------
__global__ __launch_bounds__(128)
void gla_rec_kernel()
{
    int bid = blockIdx.x;
    int dvt = bid & 7;           // which 32-wide slice of Dv
    int h   = (bid >> 3) & 3;
    int b   = bid >> 5;
    int tid = threadIdx.x;
    int c   = tid & 31;
    int qr  = tid >> 5;

    size_t base_qk = ((size_t)b * TT) * 512 + (size_t)h * 128;
    size_t base_v  = ((size_t)b * TT) * 1024 + (size_t)h * 256 + (size_t)dvt * 32;

    const float* qp = g_q   + base_qk;
    const float* kp = g_k   + base_qk;
    const float* dp = g_dcy + base_qk;
    const float* vp = g_v   + base_v;
    float*       op = g_o   + base_v;

    __shared__ float qs[128], ks[128], ds[128], vs[32], red[128];

    float S[32];
#pragma unroll
    for (int i = 0; i < 32; i++) S[i] = 0.f;

    float rq = qp[tid], rk = kp[tid], rd = dp[tid];
    float rv = (tid < 32) ? vp[tid] : 0.f;

    for (int t = 0; t < TT; t++) {
        qs[tid] = rq; ks[tid] = rk; ds[tid] = rd;
        if (tid < 32) vs[tid] = rv;
        __syncthreads();

        if (t + 1 < TT) {                       // prefetch next step
            size_t off = (size_t)(t + 1) * 512 + tid;
            rq = qp[off]; rk = kp[off]; rd = dp[off];
            if (tid < 32) rv = vp[(size_t)(t + 1) * 1024 + tid];
        }

        float vj = vs[c];
        const float* qq = &qs[qr * 32];
        const float* kq = &ks[qr * 32];
        const float* dq = &ds[qr * 32];
        float a0 = 0.f, a1 = 0.f, a2 = 0.f, a3 = 0.f;
#pragma unroll
        for (int i = 0; i < 32; i += 4) {
            S[i + 0] = dq[i + 0] * S[i + 0] + kq[i + 0] * vj;  a0 += qq[i + 0] * S[i + 0];
            S[i + 1] = dq[i + 1] * S[i + 1] + kq[i + 1] * vj;  a1 += qq[i + 1] * S[i + 1];
            S[i + 2] = dq[i + 2] * S[i + 2] + kq[i + 2] * vj;  a2 += qq[i + 2] * S[i + 2];
            S[i + 3] = dq[i + 3] * S[i + 3] + kq[i + 3] * vj;  a3 += qq[i + 3] * S[i + 3];
        }
        red[tid] = (a0 + a1) + (a2 + a3);
        __syncthreads();

        if (qr == 0)
            op[(size_t)t * 1024 + c] = red[c] + red[c + 32] + red[c + 64] + red[c + 96];
    }
}

// ---------------------------------------------------------------------------
// Epilogue: per (m, head): o = o * rsqrt(mean(o^2)+eps) * g_norm_w * g*sigmoid(g)
// One row per block, one warp per head, 8 cols per lane. In-place on g_o.
// ---------------------------------------------------------------------------
__global__ __launch_bounds__(128)
void epilogue_kernel(const float* __restrict__ g, const float* __restrict__ gnw)
{
    int m    = blockIdx.x;
    int wid  = threadIdx.x >> 5;
    int lane = threadIdx.x & 31;
    size_t off = (size_t)m * 1024 + (size_t)wid * 256 + (size_t)lane * 8;

    float4 o0 = *(const float4*)(g_o + off);
    float4 o1 = *(const float4*)(g_o + off + 4);
    float ssq = o0.x * o0.x + o0.y * o0.y + o0.z * o0.z + o0.w * o0.w
              + o1.x * o1.x + o1.y * o1.y + o1.z * o1.z + o1.w * o1.w;
#pragma unroll
    for (int s = 16; s > 0; s >>= 1)
        ssq += __shfl_xor_sync(0xffffffffu, ssq, s);
    float rms = rsqrtf(ssq * (1.f / 256.f) + 1e-5f);

    float4 gg0 = *(const float4*)(g + off);
    float4 gg1 = *(const float4*)(g + off + 4);
    const float* w = gnw + lane * 8;

    float4 r0, r1;
    r0.x = o0.x * rms * w[0] * (gg0.x / (1.f + expf(-gg0.x)));
    r0.y = o0.y * rms * w[1] * (gg0.y / (1.f + expf(-gg0.y)));
    r0.z = o0.z * rms * w[2] * (gg0.z / (1.f + expf(-gg0.z)));
    r0.w = o0.w * rms * w[3] * (gg0.w / (1.f + expf(-gg0.w)));
    r1.x = o1.x * rms * w[4] * (gg1.x / (1.f + expf(-gg1.x)));
    r1.y = o1.y * rms * w[5] * (gg1.y / (1.f + expf(-gg1.y)));
    r1.z = o1.z * rms * w[6] * (gg1.z / (1.f + expf(-gg1.z)));
    r1.w = o1.w * rms * w[7] * (gg1.w / (1.f + expf(-gg1.w)));

    *(float4*)(g_o + off)     = r0;
    *(float4*)(g_o + off + 4) = r1;
}

// ---------------------------------------------------------------------------
extern "C" void kernel_launch(void* const* d_in, const int* in_sizes, int n_in,
                              void* d_out, int out_size)
{
    (void)in_sizes; (void)n_in; (void)out_size;
    const float* x     = (const float*)d_in[0];
    const float* Wq    = (const float*)d_in[1];
    const float* Wk    = (const float*)d_in[2];
    const float* Wv    = (const float*)d_in[3];
    const float* gk_w1 = (const float*)d_in[4];
    const float* gk_w2 = (const float*)d_in[5];
    const float* gk_b2 = (const float*)d_in[6];
    const float* Wg    = (const float*)d_in[7];
    const float* gnw   = (const float*)d_in[8];
    const float* Wo    = (const float*)d_in[9];
    float* out = (float*)d_out;

    float *pq, *pk, *pv, *pg, *pd, *po, *pweff;
    cudaGetSymbolAddress((void**)&pq,    g_q);
    cudaGetSymbolAddress((void**)&pk,    g_k);
    cudaGetSymbolAddress((void**)&pv,    g_v);
    cudaGetSymbolAddress((void**)&pg,    g_g);
    cudaGetSymbolAddress((void**)&pd,    g_dcy);
    cudaGetSymbolAddress((void**)&po,    g_o);
    cudaGetSymbolAddress((void**)&pweff, g_weff);

    dim3 blk(256);
    dim3 grid512(512 / 128, MM / 128);    // (4, 256)
    dim3 grid1024(1024 / 128, MM / 128);  // (8, 256)

    // low-rank gate collapsed into one effective weight
    weff_kernel<<<(1024 * 512) / 256, 256>>>(gk_w1, gk_w2);

    sgemm_k<<<grid512,  blk>>>(x, Wq,    pq, DD, 512,  QSCALE, nullptr, 0);
    sgemm_k<<<grid512,  blk>>>(x, Wk,    pk, DD, 512,  1.f,    nullptr, 0);
    sgemm_k<<<grid1024, blk>>>(x, Wv,    pv, DD, 1024, 1.f,    nullptr, 0);
    sgemm_k<<<grid1024, blk>>>(x, Wg,    pg, DD, 1024, 1.f,    nullptr, 0);
    sgemm_k<<<grid512,  blk>>>(x, pweff, pd, DD, 512,  1.f,    gk_b2,  1);

    gla_rec_kernel<<<BB * HH * (DV / 32), 128>>>();

    epilogue_kernel<<<MM, 128>>>(pg, gnw);

    sgemm_k<<<grid1024, blk>>>(po, Wo, out, DD, 1024, 1.f, nullptr, 0);
}

// round 2
// speedup vs baseline: 1.9719x; 1.9719x over previous
#include <cuda_runtime.h>
#include <cuda_bf16.h>
#include <cstdint>

// ---------------------------------------------------------------------------
// GLA block: B=8, T=4096, D=1024, H=4, Dk=128, Dv=256
// GEMMs via mma.sync bf16 3-term split (Ah*Bh + Ah*Bl + Al*Bh) ~= fp32 accuracy
// ---------------------------------------------------------------------------

#define BB   8
#define TT   4096
#define MM   (BB*TT)          // 32768
#define QSCALE 0.08838834764831845f

// ---------------- scratch (device globals; allocation-free) ----------------
__device__ __nv_bfloat16 g_xh[MM*1024], g_xl[MM*1024];
__device__ __nv_bfloat16 g_wqh[1024*512],  g_wql[1024*512];
__device__ __nv_bfloat16 g_wkh[1024*512],  g_wkl[1024*512];
__device__ __nv_bfloat16 g_wvh[1024*1024], g_wvl[1024*1024];
__device__ __nv_bfloat16 g_wgh[1024*1024], g_wgl[1024*1024];
__device__ __nv_bfloat16 g_w_oh[1024*1024], g_w_ol[1024*1024];   // Wo
__device__ __nv_bfloat16 g_wdh[1024*512],  g_wdl[1024*512];      // Weff = gk_w1@gk_w2
__device__ float g_q[MM*512], g_k[MM*512], g_dcy[MM*512];
__device__ float g_v[MM*1024], g_g[MM*1024], g_o[MM*1024];
__device__ __nv_bfloat16 g_oh[MM*1024], g_ol[MM*1024];

// ---------------------------------------------------------------------------
// fp32 -> (bf16 hi, bf16 lo) split, vectorized
// ---------------------------------------------------------------------------
__global__ void split_kernel(const float* __restrict__ s,
                             __nv_bfloat16* __restrict__ h,
                             __nv_bfloat16* __restrict__ l, int n)
{
    int i = (blockIdx.x * blockDim.x + threadIdx.x) * 4;
    if (i >= n) return;
    float4 v = *(const float4*)(s + i);
    __nv_bfloat16 h0 = __float2bfloat16_rn(v.x);
    __nv_bfloat16 h1 = __float2bfloat16_rn(v.y);
    __nv_bfloat16 h2 = __float2bfloat16_rn(v.z);
    __nv_bfloat16 h3 = __float2bfloat16_rn(v.w);
    __nv_bfloat16 l0 = __float2bfloat16_rn(v.x - __bfloat162float(h0));
    __nv_bfloat16 l1 = __float2bfloat16_rn(v.y - __bfloat162float(h1));
    __nv_bfloat16 l2 = __float2bfloat16_rn(v.z - __bfloat162float(h2));
    __nv_bfloat16 l3 = __float2bfloat16_rn(v.w - __bfloat162float(h3));
    ((__nv_bfloat162*)(h + i))[0] = __halves2bfloat162(h0, h1);
    ((__nv_bfloat162*)(h + i))[1] = __halves2bfloat162(h2, h3);
    ((__nv_bfloat162*)(l + i))[0] = __halves2bfloat162(l0, l1);
    ((__nv_bfloat162*)(l + i))[1] = __halves2bfloat162(l2, l3);
}

// Weff = gk_w1 @ gk_w2 (1024x16 @ 16x512), split directly to bf16 hi/lo
__global__ void weff_split_kernel(const float* __restrict__ w1,
                                  const float* __restrict__ w2)
{
    int idx = blockIdx.x * blockDim.x + threadIdx.x;   // < 1024*512
    int kk = idx >> 9;
    int n  = idx & 511;
    float s = 0.f;
#pragma unroll
    for (int r = 0; r < 16; r++)
        s += w1[kk * 16 + r] * w2[r * 512 + n];
    __nv_bfloat16 h = __float2bfloat16_rn(s);
    g_wdh[idx] = h;
    g_wdl[idx] = __float2bfloat16_rn(s - __bfloat162float(h));
}

// ---------------------------------------------------------------------------
// bf16 split-GEMM: C[M,N] = (Ah+Al)[M,K] @ (Bh+Bl)[K,N] (drops Al*Bl)
// BM=BN=128, BK=32, 256 thr, warp grid 2x4, warp tile 64x32, cp.async 2-stage
// mode 0: C = acc*scale ; mode 1: decay transform with bias
// ---------------------------------------------------------------------------
#define A_T 5120   // 128*40 elems per stage
#define B_T 4352   // 32*136 elems per stage
#define SMEM_BYTES ((4*A_T + 4*B_T) * 2)

__device__ __forceinline__ void cp16(uint32_t s, const void* g) {
    asm volatile("cp.async.cg.shared.global [%0], [%1], 16;" :: "r"(s), "l"(g));
}
#define LDSM_X4(R0,R1,R2,R3,ADDR) \
    asm volatile("ldmatrix.sync.aligned.m8n8.x4.shared.b16 {%0,%1,%2,%3}, [%4];" \
        : "=r"(R0),"=r"(R1),"=r"(R2),"=r"(R3) : "r"(ADDR))
#define LDSM_X4T(R0,R1,R2,R3,ADDR) \
    asm volatile("ldmatrix.sync.aligned.m8n8.x4.trans.shared.b16 {%0,%1,%2,%3}, [%4];" \
        : "=r"(R0),"=r"(R1),"=r"(R2),"=r"(R3) : "r"(ADDR))
#define MMA(D,A,B) \
    asm volatile("mma.sync.aligned.m16n8k16.row.col.f32.bf16.bf16.f32 " \
        "{%0,%1,%2,%3}, {%4,%5,%6,%7}, {%8,%9}, {%0,%1,%2,%3};" \
        : "+f"(D[0]),"+f"(D[1]),"+f"(D[2]),"+f"(D[3]) \
        : "r"(A[0]),"r"(A[1]),"r"(A[2]),"r"(A[3]),"r"(B[0]),"r"(B[1]))

__global__ __launch_bounds__(256)
void hgemm3(const __nv_bfloat16* __restrict__ Ah, const __nv_bfloat16* __restrict__ Al,
            const __nv_bfloat16* __restrict__ Bh, const __nv_bfloat16* __restrict__ Bl,
            float* __restrict__ C, int K, int N, float scale,
            const float* __restrict__ bias, int mode)
{
    extern __shared__ __align__(16) __nv_bfloat16 sm[];
    __nv_bfloat16* sAh = sm;
    __nv_bfloat16* sAl = sm + 2*A_T;
    __nv_bfloat16* sBh = sm + 4*A_T;
    __nv_bfloat16* sBl = sm + 4*A_T + 2*B_T;

    const int tid = threadIdx.x;
    const int bn = blockIdx.x, bm = blockIdx.y;
    const int lane = tid & 31, wid = tid >> 5;
    const int wm = (wid & 1) * 64;
    const int wn = (wid >> 1) * 32;

    // global->smem load indices
    const int ar = tid >> 2;             // 0..63
    const int ac = (tid & 3) * 8;        // 0,8,16,24
    const int br = tid >> 4;             // 0..15
    const int bc = (tid & 15) * 8;       // 0..120

    const __nv_bfloat16* gAh = Ah + (size_t)(bm*128 + ar) * K + ac;
    const __nv_bfloat16* gAl = Al + (size_t)(bm*128 + ar) * K + ac;
    const __nv_bfloat16* gBh = Bh + (size_t)br * N + bn*128 + bc;
    const __nv_bfloat16* gBl = Bl + (size_t)br * N + bn*128 + bc;

    const uint32_t uAh = (uint32_t)__cvta_generic_to_shared(sAh);
    const uint32_t uAl = (uint32_t)__cvta_generic_to_shared(sAl);
    const uint32_t uBh = (uint32_t)__cvta_generic_to_shared(sBh);
    const uint32_t uBl = (uint32_t)__cvta_generic_to_shared(sBl);
    const uint32_t a_st0 = (ar*40 + ac)*2, a_st1 = ((ar+64)*40 + ac)*2;
    const uint32_t b_st0 = (br*136 + bc)*2, b_st1 = ((br+16)*136 + bc)*2;

    float acc[4][4][4];
#pragma unroll
    for (int i = 0; i < 4; i++)
#pragma unroll
        for (int j = 0; j < 4; j++)
#pragma unroll
            for (int r = 0; r < 4; r++) acc[i][j][r] = 0.f;

    const int KT = K >> 5;

    auto load_stage = [&](int kt, int st) {
        const __nv_bfloat16* pAh = gAh + kt*32;
        const __nv_bfloat16* pAl = gAl + kt*32;
        const __nv_bfloat16* pBh = gBh + (size_t)kt*32*N;
        const __nv_bfloat16* pBl = gBl + (size_t)kt*32*N;
        uint32_t ao = st * (A_T*2), bo = st * (B_T*2);
        cp16(uAh + ao + a_st0, pAh);
        cp16(uAh + ao + a_st1, pAh + (size_t)64*K);
        cp16(uAl + ao + a_st0, pAl);
        cp16(uAl + ao + a_st1, pAl + (size_t)64*K);
        cp16(uBh + bo + b_st0, pBh);
        cp16(uBh + bo + b_st1, pBh + (size_t)16*N);
        cp16(uBl + bo + b_st0, pBl);
        cp16(uBl + bo + b_st1, pBl + (size_t)16*N);
        asm volatile("cp.async.commit_group;");
    };

    const int arow = wm + (lane & 15);
    const int acol = (lane >> 4) * 8;
    const int bkr  = (lane & 15);
    const int bcol = wn + ((lane >> 4) * 8);

    load_stage(0, 0);
    for (int kt = 0; kt < KT; kt++) {
        asm volatile("cp.async.wait_group 0;" ::: "memory");
        __syncthreads();
        if (kt + 1 < KT) load_stage(kt + 1, (kt + 1) & 1);

        int st = kt & 1;
        uint32_t aBH = uAh + st*(A_T*2), aBL = uAl + st*(A_T*2);
        uint32_t bBH = uBh + st*(B_T*2), bBL = uBl + st*(B_T*2);
#pragma unroll
        for (int ks = 0; ks < 2; ks++) {
            uint32_t ah[4][4], al[4][4], bh[4][2], bl[4][2];
#pragma unroll
            for (int mi = 0; mi < 4; mi++) {
                uint32_t off = ((arow + mi*16)*40 + ks*16 + acol) * 2;
                LDSM_X4(ah[mi][0], ah[mi][1], ah[mi][2], ah[mi][3], aBH + off);
                LDSM_X4(al[mi][0], al[mi][1], al[mi][2], al[mi][3], aBL + off);
            }
#pragma unroll
            for (int p = 0; p < 2; p++) {
                uint32_t off = ((ks*16 + bkr)*136 + bcol + p*16) * 2;
                LDSM_X4T(bh[2*p][0], bh[2*p][1], bh[2*p+1][0], bh[2*p+1][1], bBH + off);
                LDSM_X4T(bl[2*p][0], bl[2*p][1], bl[2*p+1][0], bl[2*p+1][1], bBL + off);
            }
#pragma unroll
            for (int mi = 0; mi < 4; mi++)
#pragma unroll
                for (int ni = 0; ni < 4; ni++) MMA(acc[mi][ni], ah[mi], bh[ni]);
#pragma unroll
            for (int mi = 0; mi < 4; mi++)
#pragma unroll
                for (int ni = 0; ni < 4; ni++) MMA(acc[mi][ni], ah[mi], bl[ni]);
#pragma unroll
            for (int mi = 0; mi < 4; mi++)
#pragma unroll
                for (int ni = 0; ni < 4; ni++) MMA(acc[mi][ni], al[mi], bh[ni]);
        }
    }

    // epilogue
#pragma unroll
    for (int mi = 0; mi < 4; mi++) {
        int r0 = bm*128 + wm + mi*16 + (lane >> 2);
#pragma unroll
        for (int ni = 0; ni < 4; ni++) {
            int c = bn*128 + wn + ni*8 + (lane & 3)*2;
            float o0 = acc[mi][ni][0], o1 = acc[mi][ni][1];
            float o2 = acc[mi][ni][2], o3 = acc[mi][ni][3];
            if (mode == 0) {
                o0 *= scale; o1 *= scale; o2 *= scale; o3 *= scale;
            } else {
                float b0 = bias[c], b1 = bias[c + 1];
                float z, sp;
                z = o0 + b0; sp = fmaxf(-z,0.f) + log1pf(expf(-fabsf(z))); o0 = expf(-sp*0.0625f);
                z = o1 + b1; sp = fmaxf(-z,0.f) + log1pf(expf(-fabsf(z))); o1 = expf(-sp*0.0625f);
                z = o2 + b0; sp = fmaxf(-z,0.f) + log1pf(expf(-fabsf(z))); o2 = expf(-sp*0.0625f);
                z = o3 + b1; sp = fmaxf(-z,0.f) + log1pf(expf(-fabsf(z))); o3 = expf(-sp*0.0625f);
            }
            *(float2*)(C + (size_t)r0 * N + c)       = make_float2(o0, o1);
            *(float2*)(C + (size_t)(r0 + 8) * N + c) = make_float2(o2, o3);
        }
    }
}

// ---------------------------------------------------------------------------
// GLA recurrence (unchanged from round 1 — correct, ~1.4ms)
// ---------------------------------------------------------------------------
__global__ __launch_bounds__(128)
void gla_rec_kernel()
{
    int bid = blockIdx.x;
    int dvt = bid & 7;
    int h   = (bid >> 3) & 3;
    int b   = bid >> 5;
    int tid = threadIdx.x;
    int c   = tid & 31;
    int qr  = tid >> 5;

    size_t base_qk = ((size_t)b * TT) * 512 + (size_t)h * 128;
    size_t base_v  = ((size_t)b * TT) * 1024 + (size_t)h * 256 + (size_t)dvt * 32;

    const float* qp = g_q   + base_qk;
    const float* kp = g_k   + base_qk;
    const float* dp = g_dcy + base_qk;
    const float* vp = g_v   + base_v;
    float*       op = g_o   + base_v;

    __shared__ float qs[128], ks[128], ds[128], vs[32], red[128];

    float S[32];
#pragma unroll
    for (int i = 0; i < 32; i++) S[i] = 0.f;

    float rq = qp[tid], rk = kp[tid], rd = dp[tid];
    float rv = (tid < 32) ? vp[tid] : 0.f;

    for (int t = 0; t < TT; t++) {
        qs[tid] = rq; ks[tid] = rk; ds[tid] = rd;
        if (tid < 32) vs[tid] = rv;
        __syncthreads();

        if (t + 1 < TT) {
            size_t off = (size_t)(t + 1) * 512 + tid;
            rq = qp[off]; rk = kp[off]; rd = dp[off];
            if (tid < 32) rv = vp[(size_t)(t + 1) * 1024 + tid];
        }

        float vj = vs[c];
        const float* qq = &qs[qr * 32];
        const float* kq = &ks[qr * 32];
        const float* dq = &ds[qr * 32];
        float a0 = 0.f, a1 = 0.f, a2 = 0.f, a3 = 0.f;
#pragma unroll
        for (int i = 0; i < 32; i += 4) {
            S[i + 0] = dq[i + 0] * S[i + 0] + kq[i + 0] * vj;  a0 += qq[i + 0] * S[i + 0];
            S[i + 1] = dq[i + 1] * S[i + 1] + kq[i + 1] * vj;  a1 += qq[i + 1] * S[i + 1];
            S[i + 2] = dq[i + 2] * S[i + 2] + kq[i + 2] * vj;  a2 += qq[i + 2] * S[i + 2];
            S[i + 3] = dq[i + 3] * S[i + 3] + kq[i + 3] * vj;  a3 += qq[i + 3] * S[i + 3];
        }
        red[tid] = (a0 + a1) + (a2 + a3);
        __syncthreads();

        if (qr == 0)
            op[(size_t)t * 1024 + c] = red[c] + red[c + 32] + red[c + 64] + red[c + 96];
    }
}

// ---------------------------------------------------------------------------
// Epilogue: RMSNorm * g_norm_w * swish(g); writes bf16 hi/lo for final GEMM
// ---------------------------------------------------------------------------
__global__ __launch_bounds__(128)
void epilogue_kernel(const float* __restrict__ g, const float* __restrict__ gnw)
{
    int m    = blockIdx.x;
    int wid  = threadIdx.x >> 5;
    int lane = threadIdx.x & 31;
    size_t off = (size_t)m * 1024 + (size_t)wid * 256 + (size_t)lane * 8;

    float4 o0 = *(const float4*)(g_o + off);
    float4 o1 = *(const float4*)(g_o + off + 4);
    float ssq = o0.x * o0.x + o0.y * o0.y + o0.z * o0.z + o0.w * o0.w
              + o1.x * o1.x + o1.y * o1.y + o1.z * o1.z + o1.w * o1.w;
#pragma unroll
    for (int s = 16; s > 0; s >>= 1)
        ssq += __shfl_xor_sync(0xffffffffu, ssq, s);
    float rms = rsqrtf(ssq * (1.f / 256.f) + 1e-5f);

    float4 gg0 = *(const float4*)(g + off);
    float4 gg1 = *(const float4*)(g + off + 4);
    const float* w = gnw + lane * 8;

    float r[8];
    r[0] = o0.x * rms * w[0] * (gg0.x / (1.f + expf(-gg0.x)));
    r[1] = o0.y * rms * w[1] * (gg0.y / (1.f + expf(-gg0.y)));
    r[2] = o0.z * rms * w[2] * (gg0.z / (1.f + expf(-gg0.z)));
    r[3] = o0.w * rms * w[3] * (gg0.w / (1.f + expf(-gg0.w)));
    r[4] = o1.x * rms * w[4] * (gg1.x / (1.f + expf(-gg1.x)));
    r[5] = o1.y * rms * w[5] * (gg1.y / (1.f + expf(-gg1.y)));
    r[6] = o1.z * rms * w[6] * (gg1.z / (1.f + expf(-gg1.z)));
    r[7] = o1.w * rms * w[7] * (gg1.w / (1.f + expf(-gg1.w)));

#pragma unroll
    for (int i = 0; i < 8; i += 2) {
        __nv_bfloat16 h0 = __float2bfloat16_rn(r[i]);
        __nv_bfloat16 h1 = __float2bfloat16_rn(r[i+1]);
        __nv_bfloat16 l0 = __float2bfloat16_rn(r[i]   - __bfloat162float(h0));
        __nv_bfloat16 l1 = __float2bfloat16_rn(r[i+1] - __bfloat162float(h1));
        *(__nv_bfloat162*)(g_oh + off + i) = __halves2bfloat162(h0, h1);
        *(__nv_bfloat162*)(g_ol + off + i) = __halves2bfloat162(l0, l1);
    }
}

// ---------------------------------------------------------------------------
extern "C" void kernel_launch(void* const* d_in, const int* in_sizes, int n_in,
                              void* d_out, int out_size)
{
    (void)in_sizes; (void)n_in; (void)out_size;
    const float* x     = (const float*)d_in[0];
    const float* Wq    = (const float*)d_in[1];
    const float* Wk    = (const float*)d_in[2];
    const float* Wv    = (const float*)d_in[3];
    const float* gk_w1 = (const float*)d_in[4];
    const float* gk_w2 = (const float*)d_in[5];
    const float* gk_b2 = (const float*)d_in[6];
    const float* Wg    = (const float*)d_in[7];
    const float* gnw   = (const float*)d_in[8];
    const float* Wo    = (const float*)d_in[9];
    float* out = (float*)d_out;

    __nv_bfloat16 *xh, *xl, *wqh, *wql, *wkh, *wkl, *wvh, *wvl, *wgh, *wgl,
                  *woh, *wol, *wdh, *wdl, *oh, *ol;
    float *pq, *pk, *pd, *pv, *pg, *po;
    cudaGetSymbolAddress((void**)&xh,  g_xh);  cudaGetSymbolAddress((void**)&xl,  g_xl);
    cudaGetSymbolAddress((void**)&wqh, g_wqh); cudaGetSymbolAddress((void**)&wql, g_wql);
    cudaGetSymbolAddress((void**)&wkh, g_wkh); cudaGetSymbolAddress((void**)&wkl, g_wkl);
    cudaGetSymbolAddress((void**)&wvh, g_wvh); cudaGetSymbolAddress((void**)&wvl, g_wvl);
    cudaGetSymbolAddress((void**)&wgh, g_wgh); cudaGetSymbolAddress((void**)&wgl, g_wgl);
    cudaGetSymbolAddress((void**)&woh, g_w_oh); cudaGetSymbolAddress((void**)&wol, g_w_ol);
    cudaGetSymbolAddress((void**)&wdh, g_wdh); cudaGetSymbolAddress((void**)&wdl, g_wdl);
    cudaGetSymbolAddress((void**)&oh,  g_oh);  cudaGetSymbolAddress((void**)&ol,  g_ol);
    cudaGetSymbolAddress((void**)&pq,  g_q);   cudaGetSymbolAddress((void**)&pk,  g_k);
    cudaGetSymbolAddress((void**)&pd,  g_dcy); cudaGetSymbolAddress((void**)&pv,  g_v);
    cudaGetSymbolAddress((void**)&pg,  g_g);   cudaGetSymbolAddress((void**)&po,  g_o);

    cudaFuncSetAttribute(hgemm3, cudaFuncAttributeMaxDynamicSharedMemorySize, SMEM_BYTES);

    // splits
    split_kernel<<<(MM*1024/4 + 255)/256, 256>>>(x,  xh,  xl,  MM*1024);
    split_kernel<<<(1024*512/4 + 255)/256, 256>>>(Wq, wqh, wql, 1024*512);
    split_kernel<<<(1024*512/4 + 255)/256, 256>>>(Wk, wkh, wkl, 1024*512);
    split_kernel<<<(1024*1024/4 + 255)/256, 256>>>(Wv, wvh, wvl, 1024*1024);
    split_kernel<<<(1024*1024/4 + 255)/256, 256>>>(Wg, wgh, wgl, 1024*1024);
    split_kernel<<<(1024*1024/4 + 255)/256, 256>>>(Wo, woh, wol, 1024*1024);
    weff_split_kernel<<<(1024*512)/256, 256>>>(gk_w1, gk_w2);

    dim3 blk(256);
    dim3 g512(4, MM/128);
    dim3 g1024(8, MM/128);

    hgemm3<<<g512,  blk, SMEM_BYTES>>>(xh, xl, wqh, wql, pq, 1024, 512,  QSCALE, nullptr, 0);
    hgemm3<<<g512,  blk, SMEM_BYTES>>>(xh, xl, wkh, wkl, pk, 1024, 512,  1.f,    nullptr, 0);
    hgemm3<<<g1024, blk, SMEM_BYTES>>>(xh, xl, wvh, wvl, pv, 1024, 1024, 1.f,    nullptr, 0);
    hgemm3<<<g1024, blk, SMEM_BYTES>>>(xh, xl, wgh, wgl, pg, 1024, 1024, 1.f,    nullptr, 0);
    hgemm3<<<g512,  blk, SMEM_BYTES>>>(xh, xl, wdh, wdl, pd, 1024, 512,  1.f,    gk_b2, 1);

    gla_rec_kernel<<<BB * 4 * 8, 128>>>();

    epilogue_kernel<<<MM, 128>>>(pg, gnw);

    hgemm3<<<g1024, blk, SMEM_BYTES>>>(oh, ol, woh, wol, out, 1024, 1024, 1.f, nullptr, 0);
}